// round 7
// baseline (speedup 1.0000x reference)
#include <cuda_runtime.h>
#include <math.h>

// Problem constants
#define BB   2
#define SS   2048
#define DM   2048
#define NH   32
#define NKV  8
#define DH   64
#define MTOK (BB*SS)        // 4096 tokens total

// Scratch (device globals: allocation-free rule)
__device__ float g_q[MTOK * (NH*DH)];      // [m][h*64+d]  32MB
__device__ float g_k[MTOK * (NKV*DH)];     // 8MB
__device__ float g_v[MTOK * (NKV*DH)];     // 8MB
__device__ float g_attn[MTOK * (NH*DH)];   // 32MB

// =====================================================================
// GEMM NT:  C[M,N] = A[M,K] @ Bw[N,K]^T      (QKV projections)
// 128x128x16 tiles, 256 threads, 8x8 microtile
// =====================================================================
__global__ __launch_bounds__(256)
void gemm_nt(const float* __restrict__ A, const float* __restrict__ Bw,
             float* __restrict__ C, int M, int N, int K) {
    __shared__ float As[16][128];
    __shared__ float Bs[16][128];
    const int tid = threadIdx.x;
    const int tx = tid & 15, ty = tid >> 4;
    const int row0 = blockIdx.y * 128, col0 = blockIdx.x * 128;

    // load mapping: each thread loads 2 float4 of A and 2 of B per k-tile
    const int lr = tid >> 2;            // 0..63
    const int lc = (tid & 3) << 2;      // 0,4,8,12

    const float* Ap0 = A  + (size_t)(row0 + lr) * K + lc;
    const float* Ap1 = Ap0 + (size_t)64 * K;
    const float* Bp0 = Bw + (size_t)(col0 + lr) * K + lc;
    const float* Bp1 = Bp0 + (size_t)64 * K;

    float acc[8][8];
    #pragma unroll
    for (int r = 0; r < 8; r++)
        #pragma unroll
        for (int c = 0; c < 8; c++) acc[r][c] = 0.f;

    for (int k0 = 0; k0 < K; k0 += 16) {
        float4 a0 = *(const float4*)(Ap0 + k0);
        float4 a1 = *(const float4*)(Ap1 + k0);
        float4 b0 = *(const float4*)(Bp0 + k0);
        float4 b1 = *(const float4*)(Bp1 + k0);
        __syncthreads();
        As[lc+0][lr] = a0.x; As[lc+1][lr] = a0.y; As[lc+2][lr] = a0.z; As[lc+3][lr] = a0.w;
        As[lc+0][lr+64] = a1.x; As[lc+1][lr+64] = a1.y; As[lc+2][lr+64] = a1.z; As[lc+3][lr+64] = a1.w;
        Bs[lc+0][lr] = b0.x; Bs[lc+1][lr] = b0.y; Bs[lc+2][lr] = b0.z; Bs[lc+3][lr] = b0.w;
        Bs[lc+0][lr+64] = b1.x; Bs[lc+1][lr+64] = b1.y; Bs[lc+2][lr+64] = b1.z; Bs[lc+3][lr+64] = b1.w;
        __syncthreads();
        #pragma unroll
        for (int kk = 0; kk < 16; kk++) {
            float4 fa0 = *(const float4*)&As[kk][ty*8];
            float4 fa1 = *(const float4*)&As[kk][ty*8+4];
            float4 fb0 = *(const float4*)&Bs[kk][tx*8];
            float4 fb1 = *(const float4*)&Bs[kk][tx*8+4];
            float ar[8] = {fa0.x,fa0.y,fa0.z,fa0.w,fa1.x,fa1.y,fa1.z,fa1.w};
            float br[8] = {fb0.x,fb0.y,fb0.z,fb0.w,fb1.x,fb1.y,fb1.z,fb1.w};
            #pragma unroll
            for (int r = 0; r < 8; r++)
                #pragma unroll
                for (int c = 0; c < 8; c++)
                    acc[r][c] += ar[r] * br[c];
        }
    }
    #pragma unroll
    for (int r = 0; r < 8; r++) {
        float* crow = C + (size_t)(row0 + ty*8 + r) * N + col0 + tx*8;
        *(float4*)crow       = make_float4(acc[r][0], acc[r][1], acc[r][2], acc[r][3]);
        *(float4*)(crow + 4) = make_float4(acc[r][4], acc[r][5], acc[r][6], acc[r][7]);
    }
}

// =====================================================================
// GEMM NN:  C[M,N] = A[M,K] @ Bmat[K,N]      (output projection)
// =====================================================================
__global__ __launch_bounds__(256)
void gemm_nn(const float* __restrict__ A, const float* __restrict__ Bmat,
             float* __restrict__ C, int M, int N, int K) {
    __shared__ float As[16][128];
    __shared__ float Bs[16][128];
    const int tid = threadIdx.x;
    const int tx = tid & 15, ty = tid >> 4;
    const int row0 = blockIdx.y * 128, col0 = blockIdx.x * 128;

    const int lr = tid >> 2;            // 0..63 (A rows)
    const int lc = (tid & 3) << 2;      // 0,4,8,12 (A k-cols)
    const int bkk = tid >> 5;           // 0..7  (B k-rows)
    const int bn  = (tid & 31) << 2;    // 0..124 (B n-cols)

    const float* Ap0 = A + (size_t)(row0 + lr) * K + lc;
    const float* Ap1 = Ap0 + (size_t)64 * K;

    float acc[8][8];
    #pragma unroll
    for (int r = 0; r < 8; r++)
        #pragma unroll
        for (int c = 0; c < 8; c++) acc[r][c] = 0.f;

    for (int k0 = 0; k0 < K; k0 += 16) {
        float4 a0 = *(const float4*)(Ap0 + k0);
        float4 a1 = *(const float4*)(Ap1 + k0);
        float4 b0 = *(const float4*)(Bmat + (size_t)(k0 + bkk) * N + col0 + bn);
        float4 b1 = *(const float4*)(Bmat + (size_t)(k0 + bkk + 8) * N + col0 + bn);
        __syncthreads();
        As[lc+0][lr] = a0.x; As[lc+1][lr] = a0.y; As[lc+2][lr] = a0.z; As[lc+3][lr] = a0.w;
        As[lc+0][lr+64] = a1.x; As[lc+1][lr+64] = a1.y; As[lc+2][lr+64] = a1.z; As[lc+3][lr+64] = a1.w;
        *(float4*)&Bs[bkk][bn]   = b0;
        *(float4*)&Bs[bkk+8][bn] = b1;
        __syncthreads();
        #pragma unroll
        for (int kk = 0; kk < 16; kk++) {
            float4 fa0 = *(const float4*)&As[kk][ty*8];
            float4 fa1 = *(const float4*)&As[kk][ty*8+4];
            float4 fb0 = *(const float4*)&Bs[kk][tx*8];
            float4 fb1 = *(const float4*)&Bs[kk][tx*8+4];
            float ar[8] = {fa0.x,fa0.y,fa0.z,fa0.w,fa1.x,fa1.y,fa1.z,fa1.w};
            float br[8] = {fb0.x,fb0.y,fb0.z,fb0.w,fb1.x,fb1.y,fb1.z,fb1.w};
            #pragma unroll
            for (int r = 0; r < 8; r++)
                #pragma unroll
                for (int c = 0; c < 8; c++)
                    acc[r][c] += ar[r] * br[c];
        }
    }
    #pragma unroll
    for (int r = 0; r < 8; r++) {
        float* crow = C + (size_t)(row0 + ty*8 + r) * N + col0 + tx*8;
        *(float4*)crow       = make_float4(acc[r][0], acc[r][1], acc[r][2], acc[r][3]);
        *(float4*)(crow + 4) = make_float4(acc[r][4], acc[r][5], acc[r][6], acc[r][7]);
    }
}

// =====================================================================
// Flash attention: causal, online softmax.
// Grid: (S/64, NH, B). 256 threads = 16x16, 4x4 microtile on 64x64 tiles.
// Smem layouts chosen so all inner-loop LDS.128 are broadcast or contiguous.
// =====================================================================
#define PAD 68   // row stride (floats); 68*4B keeps 16B alignment, breaks bank aliasing

__global__ __launch_bounds__(256)
void attn_kernel(const float* __restrict__ gq, const float* __restrict__ gk,
                 const float* __restrict__ gv, float* __restrict__ go) {
    extern __shared__ float sm[];
    float* Qt = sm;                // [64 dim][PAD tok]  (transposed)
    float* Kt = Qt + 64*PAD;       // [64 dim][PAD key]  (transposed)
    float* Vs = Kt + 64*PAD;       // [64 key][PAD dim]  (natural)
    float* Ps = Vs + 64*PAD;       // [64 qrow][PAD key] (natural)

    const int tid = threadIdx.x;
    const int tx = tid & 15, ty = tid >> 4;
    const int qt = blockIdx.x, h = blockIdx.y, b = blockIdx.z;
    const int kvh = h >> 2;                       // repeat_interleave: head h -> kv head h/4
    const int q0 = qt * 64;

    const float* qbase = gq + (size_t)b * SS * (NH*DH)  + h   * DH;
    const float* kbase = gk + (size_t)b * SS * (NKV*DH) + kvh * DH;
    const float* vbase = gv + (size_t)b * SS * (NKV*DH) + kvh * DH;

    // Load Q tile transposed: Qt[d][tok]
    #pragma unroll
    for (int l = 0; l < 4; l++) {
        int fid = tid + l * 256;
        int row = fid >> 4;            // token 0..63
        int c4  = (fid & 15) << 2;     // dim 0..60
        float4 v = *(const float4*)(qbase + (size_t)(q0 + row) * (NH*DH) + c4);
        Qt[(c4+0)*PAD + row] = v.x;
        Qt[(c4+1)*PAD + row] = v.y;
        Qt[(c4+2)*PAD + row] = v.z;
        Qt[(c4+3)*PAD + row] = v.w;
    }

    float m_i[4], l_i[4], o[4][4];
    #pragma unroll
    for (int r = 0; r < 4; r++) {
        m_i[r] = -1e30f; l_i[r] = 0.f;
        #pragma unroll
        for (int c = 0; c < 4; c++) o[r][c] = 0.f;
    }

    for (int j = 0; j <= qt; j++) {
        const int k0 = j * 64;
        __syncthreads();   // prior iteration done reading Kt/Vs/Ps (covers Qt on first iter too)
        #pragma unroll
        for (int l = 0; l < 4; l++) {
            int fid = tid + l * 256;
            int row = fid >> 4;
            int c4  = (fid & 15) << 2;
            float4 kv = *(const float4*)(kbase + (size_t)(k0 + row) * (NKV*DH) + c4);
            Kt[(c4+0)*PAD + row] = kv.x;
            Kt[(c4+1)*PAD + row] = kv.y;
            Kt[(c4+2)*PAD + row] = kv.z;
            Kt[(c4+3)*PAD + row] = kv.w;
            float4 vv = *(const float4*)(vbase + (size_t)(k0 + row) * (NKV*DH) + c4);
            *(float4*)&Vs[row*PAD + c4] = vv;
        }
        __syncthreads();

        // S = Q K^T (64-deep dot, outer-product form)
        float s[4][4];
        #pragma unroll
        for (int r = 0; r < 4; r++)
            #pragma unroll
            for (int c = 0; c < 4; c++) s[r][c] = 0.f;
        #pragma unroll 8
        for (int kk = 0; kk < 64; kk++) {
            float4 a = *(const float4*)&Qt[kk*PAD + ty*4];
            float4 bk = *(const float4*)&Kt[kk*PAD + tx*4];
            float av[4] = {a.x, a.y, a.z, a.w};
            float bv[4] = {bk.x, bk.y, bk.z, bk.w};
            #pragma unroll
            for (int r = 0; r < 4; r++)
                #pragma unroll
                for (int c = 0; c < 4; c++)
                    s[r][c] += av[r] * bv[c];
        }

        // scale + causal mask (only diagonal tile needs masking)
        const bool diag = (j == qt);
        #pragma unroll
        for (int r = 0; r < 4; r++) {
            int qg = q0 + ty*4 + r;
            #pragma unroll
            for (int c = 0; c < 4; c++) {
                float val = s[r][c] * 0.125f;   // 1/sqrt(64)
                if (diag && (k0 + tx*4 + c) > qg) val = -1e30f;
                s[r][c] = val;
            }
        }

        // online softmax: row max across 16 tx lanes
        #pragma unroll
        for (int r = 0; r < 4; r++) {
            float mt = fmaxf(fmaxf(s[r][0], s[r][1]), fmaxf(s[r][2], s[r][3]));
            #pragma unroll
            for (int off = 8; off > 0; off >>= 1)
                mt = fmaxf(mt, __shfl_xor_sync(0xffffffffu, mt, off));
            float mnew = fmaxf(m_i[r], mt);
            float alpha = __expf(m_i[r] - mnew);
            m_i[r] = mnew;
            float rs = 0.f;
            #pragma unroll
            for (int c = 0; c < 4; c++) {
                float p = __expf(s[r][c] - mnew);
                s[r][c] = p;
                rs += p;
            }
            #pragma unroll
            for (int off = 8; off > 0; off >>= 1)
                rs += __shfl_xor_sync(0xffffffffu, rs, off);
            l_i[r] = l_i[r] * alpha + rs;
            #pragma unroll
            for (int c = 0; c < 4; c++) o[r][c] *= alpha;
        }

        // store P tile (row-major, float4)
        #pragma unroll
        for (int r = 0; r < 4; r++)
            *(float4*)&Ps[(ty*4 + r)*PAD + tx*4] =
                make_float4(s[r][0], s[r][1], s[r][2], s[r][3]);
        __syncthreads();

        // O += P V
        #pragma unroll 4
        for (int kk = 0; kk < 64; kk += 4) {
            float4 vv[4];
            #pragma unroll
            for (int i = 0; i < 4; i++)
                vv[i] = *(const float4*)&Vs[(kk+i)*PAD + tx*4];
            #pragma unroll
            for (int r = 0; r < 4; r++) {
                float4 p = *(const float4*)&Ps[(ty*4 + r)*PAD + kk];
                o[r][0] += p.x*vv[0].x + p.y*vv[1].x + p.z*vv[2].x + p.w*vv[3].x;
                o[r][1] += p.x*vv[0].y + p.y*vv[1].y + p.z*vv[2].y + p.w*vv[3].y;
                o[r][2] += p.x*vv[0].z + p.y*vv[1].z + p.z*vv[2].z + p.w*vv[3].z;
                o[r][3] += p.x*vv[0].w + p.y*vv[1].w + p.z*vv[2].w + p.w*vv[3].w;
            }
        }
    }

    // epilogue: normalize, write [b, q, h*64+d]
    #pragma unroll
    for (int r = 0; r < 4; r++) {
        float inv = 1.f / l_i[r];
        float* orow = go + (size_t)((size_t)b*SS + q0 + ty*4 + r) * (NH*DH) + h*DH + tx*4;
        *(float4*)orow = make_float4(o[r][0]*inv, o[r][1]*inv, o[r][2]*inv, o[r][3]*inv);
    }
}

// =====================================================================
// Host launcher
// =====================================================================
extern "C" void kernel_launch(void* const* d_in, const int* in_sizes, int n_in,
                              void* d_out, int out_size) {
    const float* residual = (const float*)d_in[0];
    const float* W_Q = (const float*)d_in[1];   // [32,64,2048] -> [2048,2048] (nh-major rows)
    const float* W_K = (const float*)d_in[2];   // [8,64,2048]  -> [512,2048]
    const float* W_V = (const float*)d_in[3];
    const float* W_O = (const float*)d_in[4];   // [32,64,2048] -> [2048(nh),2048(d)]
    float* out = (float*)d_out;

    float *qp, *kp, *vp, *ap;
    cudaGetSymbolAddress((void**)&qp, g_q);
    cudaGetSymbolAddress((void**)&kp, g_k);
    cudaGetSymbolAddress((void**)&vp, g_v);
    cudaGetSymbolAddress((void**)&ap, g_attn);

    // QKV projections: C = residual @ W^T
    gemm_nt<<<dim3(2048/128, MTOK/128), 256>>>(residual, W_Q, qp, MTOK, 2048, DM);
    gemm_nt<<<dim3(512/128,  MTOK/128), 256>>>(residual, W_K, kp, MTOK, 512,  DM);
    gemm_nt<<<dim3(512/128,  MTOK/128), 256>>>(residual, W_V, vp, MTOK, 512,  DM);

    // Flash attention (causal, GQA)
    const int SMEM = 4 * 64 * PAD * (int)sizeof(float);   // 69632 B
    cudaFuncSetAttribute(attn_kernel, cudaFuncAttributeMaxDynamicSharedMemorySize, SMEM);
    attn_kernel<<<dim3(SS/64, NH, BB), 256, SMEM>>>(qp, kp, vp, ap);

    // Output projection: out = attn @ W_O  (sum over nh-dim; W_O is [nh, d] row-major)
    gemm_nn<<<dim3(2048/128, MTOK/128), 256>>>(ap, W_O, out, MTOK, 2048, DM);
}

// round 9
// speedup vs baseline: 1.6861x; 1.6861x over previous
#include <cuda_runtime.h>
#include <cuda_bf16.h>
#include <math.h>
#include <stdint.h>

// Problem constants
#define BB   2
#define SS   2048
#define DM   2048
#define NH   32
#define NKV  8
#define DH   64
#define MTOK (BB*SS)        // 4096 tokens

// ---------------------------------------------------------------------
// Scratch (device globals: allocation-free rule)
// ---------------------------------------------------------------------
__device__ float g_q[MTOK * (NH*DH)];      // 32MB
__device__ float g_k[MTOK * (NKV*DH)];     // 8MB
__device__ float g_v[MTOK * (NKV*DH)];     // 8MB
__device__ float g_attn[MTOK * (NH*DH)];   // 32MB

// bf16 split buffers (hi/lo)
__device__ __nv_bfloat16 g_Rh[MTOK * DM];
__device__ __nv_bfloat16 g_Rl[MTOK * DM];
__device__ __nv_bfloat16 g_WQh[2048 * DM];
__device__ __nv_bfloat16 g_WQl[2048 * DM];
__device__ __nv_bfloat16 g_WKh[512 * DM];
__device__ __nv_bfloat16 g_WKl[512 * DM];
__device__ __nv_bfloat16 g_WVh[512 * DM];
__device__ __nv_bfloat16 g_WVl[512 * DM];
__device__ __nv_bfloat16 g_WOTh[2048 * 2048];   // W_O transposed: [d][nh]
__device__ __nv_bfloat16 g_WOTl[2048 * 2048];
__device__ __nv_bfloat16 g_Ah[MTOK * (NH*DH)];
__device__ __nv_bfloat16 g_Al[MTOK * (NH*DH)];

// ---------------------------------------------------------------------
// helpers
// ---------------------------------------------------------------------
__device__ __forceinline__ uint32_t smem_u32(const void* p) {
    uint32_t a;
    asm("{ .reg .u64 t; cvta.to.shared.u64 t, %1; cvt.u32.u64 %0, t; }" : "=r"(a) : "l"(p));
    return a;
}

__device__ __forceinline__ void cp_async16(uint32_t dst, const void* src) {
    asm volatile("cp.async.cg.shared.global [%0], [%1], 16;" :: "r"(dst), "l"(src));
}
#define CP_COMMIT()  asm volatile("cp.async.commit_group;" ::: "memory")
#define CP_WAIT1()   asm volatile("cp.async.wait_group 1;" ::: "memory")

__device__ __forceinline__ void ldsm_x4(uint32_t addr, uint32_t& r0, uint32_t& r1,
                                        uint32_t& r2, uint32_t& r3) {
    asm volatile("ldmatrix.sync.aligned.m8n8.x4.shared.b16 {%0,%1,%2,%3}, [%4];"
                 : "=r"(r0), "=r"(r1), "=r"(r2), "=r"(r3) : "r"(addr));
}

__device__ __forceinline__ void mma_bf16(float* d, const uint32_t* a, const uint32_t* b) {
    asm volatile(
        "mma.sync.aligned.m16n8k16.row.col.f32.bf16.bf16.f32 "
        "{%0,%1,%2,%3}, {%4,%5,%6,%7}, {%8,%9}, {%0,%1,%2,%3};"
        : "+f"(d[0]), "+f"(d[1]), "+f"(d[2]), "+f"(d[3])
        : "r"(a[0]), "r"(a[1]), "r"(a[2]), "r"(a[3]), "r"(b[0]), "r"(b[1]));
}

// ---------------------------------------------------------------------
// fp32 -> bf16 hi/lo split
// ---------------------------------------------------------------------
__device__ __forceinline__ void bsplit(float v, unsigned short& h, unsigned short& l) {
    __nv_bfloat16 bh = __float2bfloat16(v);
    float r = v - __bfloat162float(bh);
    __nv_bfloat16 bl = __float2bfloat16(r);
    h = *reinterpret_cast<unsigned short*>(&bh);
    l = *reinterpret_cast<unsigned short*>(&bl);
}

__global__ __launch_bounds__(256)
void split_kernel(const float* __restrict__ x, __nv_bfloat16* __restrict__ hi,
                  __nv_bfloat16* __restrict__ lo, int n4) {
    int i = blockIdx.x * 256 + threadIdx.x;
    if (i >= n4) return;
    float4 v = ((const float4*)x)[i];
    ushort4 h, l;
    bsplit(v.x, h.x, l.x); bsplit(v.y, h.y, l.y);
    bsplit(v.z, h.z, l.z); bsplit(v.w, h.w, l.w);
    ((ushort4*)hi)[i] = h;
    ((ushort4*)lo)[i] = l;
}

// W_O [nh=2048][d=2048] -> transposed split [d][nh]
__global__ __launch_bounds__(256)
void transpose_split_kernel(const float* __restrict__ W,
                            __nv_bfloat16* __restrict__ th,
                            __nv_bfloat16* __restrict__ tl) {
    __shared__ float t[32][33];
    int bx = blockIdx.x * 32, by = blockIdx.y * 32;
    int txx = threadIdx.x, tyy = threadIdx.y;   // block (32, 8)
    #pragma unroll
    for (int j = 0; j < 4; j++)
        t[tyy + 8*j][txx] = W[(size_t)(by + tyy + 8*j) * 2048 + bx + txx];
    __syncthreads();
    #pragma unroll
    for (int j = 0; j < 4; j++) {
        int orow = bx + tyy + 8*j;
        int ocol = by + txx;
        float v = t[txx][tyy + 8*j];
        unsigned short h, l;
        bsplit(v, h, l);
        th[(size_t)orow * 2048 + ocol] = *reinterpret_cast<__nv_bfloat16*>(&h);
        tl[(size_t)orow * 2048 + ocol] = *reinterpret_cast<__nv_bfloat16*>(&l);
    }
}

// ---------------------------------------------------------------------
// mma.sync bf16-split GEMM NT:  C[128,128] tile = A[128,K] @ B[128,K]^T
// 256 threads (8 warps, 2x4), warp tile 64x32, BK=64, 3-stage cp.async.
// Smem rows: 128B (64 bf16), XOR swizzle (r&7)<<4 -> conflict-free ldmatrix.
// C = Ah*Bh + Ah*Bl + Al*Bh  (bf16 3-term split)
// ---------------------------------------------------------------------
#define BK        64
#define NKCHUNK   (DM / BK)          // 32
#define TILE_B    (128 * BK * 2)     // 16384 bytes per matrix per stage
#define STG_B     (4 * TILE_B)       // Ahi,Alo,Bhi,Blo = 64KB
#define NSTAGE    3
#define GSMEM     (NSTAGE * STG_B)   // 192KB

__global__ __launch_bounds__(256)
void gemm_hmma(const __nv_bfloat16* __restrict__ Ah, const __nv_bfloat16* __restrict__ Al,
               const __nv_bfloat16* __restrict__ Bh, const __nv_bfloat16* __restrict__ Bl,
               float* __restrict__ C, int Ntot) {
    extern __shared__ char sm[];
    const uint32_t sb = smem_u32(sm);
    const int tid = threadIdx.x, wid = tid >> 5, lane = tid & 31;
    const int col0 = blockIdx.x * 128, row0 = blockIdx.y * 128;
    const int wm = (wid >> 2) * 64;      // warp row offset in tile
    const int wn = (wid & 3) * 32;       // warp col offset in tile

    const char* gAh = (const char*)Ah + (size_t)row0 * 4096;   // 2048 * 2B per row
    const char* gAl = (const char*)Al + (size_t)row0 * 4096;
    const char* gBh = (const char*)Bh + (size_t)col0 * 4096;
    const char* gBl = (const char*)Bl + (size_t)col0 * 4096;

    // per-thread cp.async mapping: 512 x 16B chunks per matrix, 2 per thread
    // idx = tid + t*256 : r = idx>>3 (0..63? no: 0..127 needs 1024) ...
    // 128 rows x 8 granules = 1024 chunks; 256 threads -> 4 chunks per thread.
    // swizzled dst offset:
    auto sw = [](int r, int g) -> uint32_t {
        return (uint32_t)(r * 128 + ((g * 16) ^ ((r & 7) << 4)));
    };

    // ldmatrix lane addressing
    const int lrow = ((lane >> 3) & 1) * 8 + (lane & 7);  // row within 16-row group
    const int lkb  = (lane >> 4) * 16;                    // 16B granule offset (k-halves)

    float acc[4][4][4];
    #pragma unroll
    for (int mt = 0; mt < 4; mt++)
        #pragma unroll
        for (int nt = 0; nt < 4; nt++)
            #pragma unroll
            for (int e = 0; e < 4; e++) acc[mt][nt][e] = 0.f;

    // stage loader
    auto load_stage = [&](int stage, int chunk) {
        uint32_t s0 = sb + stage * STG_B;
        const size_t kb0 = (size_t)chunk * 128;   // BK*2 bytes
        #pragma unroll
        for (int t = 0; t < 4; t++) {
            int idx = tid + t * 256;
            int r = idx >> 3, g = idx & 7;
            uint32_t so = sw(r, g);
            size_t go = (size_t)r * 4096 + kb0 + g * 16;
            cp_async16(s0 + 0*TILE_B + so, gAh + go);
            cp_async16(s0 + 1*TILE_B + so, gAl + go);
            cp_async16(s0 + 2*TILE_B + so, gBh + go);
            cp_async16(s0 + 3*TILE_B + so, gBl + go);
        }
    };

    load_stage(0, 0); CP_COMMIT();
    load_stage(1, 1); CP_COMMIT();

    for (int i = 0; i < NKCHUNK; i++) {
        CP_WAIT1();
        __syncthreads();
        if (i + 2 < NKCHUNK) load_stage((i + 2) % NSTAGE, i + 2);
        CP_COMMIT();

        uint32_t s0 = sb + (i % NSTAGE) * STG_B;
        uint32_t aH = s0 + 0*TILE_B, aL = s0 + 1*TILE_B;
        uint32_t bH = s0 + 2*TILE_B, bL = s0 + 3*TILE_B;

        #pragma unroll
        for (int ks = 0; ks < 4; ks++) {
            const int kb = ks * 32 + lkb;
            uint32_t ah[4][4], al[4][4];
            #pragma unroll
            for (int mt = 0; mt < 4; mt++) {
                int r = wm + mt * 16 + lrow;
                uint32_t off = (uint32_t)(r * 128 + (kb ^ ((r & 7) << 4)));
                ldsm_x4(aH + off, ah[mt][0], ah[mt][1], ah[mt][2], ah[mt][3]);
                ldsm_x4(aL + off, al[mt][0], al[mt][1], al[mt][2], al[mt][3]);
            }
            uint32_t bhr[2][4], blr[2][4];
            #pragma unroll
            for (int np = 0; np < 2; np++) {
                int r = wn + np * 16 + lrow;
                uint32_t off = (uint32_t)(r * 128 + (kb ^ ((r & 7) << 4)));
                ldsm_x4(bH + off, bhr[np][0], bhr[np][1], bhr[np][2], bhr[np][3]);
                ldsm_x4(bL + off, blr[np][0], blr[np][1], blr[np][2], blr[np][3]);
            }
            #pragma unroll
            for (int mt = 0; mt < 4; mt++) {
                #pragma unroll
                for (int nt = 0; nt < 4; nt++) {
                    uint32_t bh2[2] = { bhr[nt >> 1][nt & 1], bhr[nt >> 1][2 + (nt & 1)] };
                    uint32_t bl2[2] = { blr[nt >> 1][nt & 1], blr[nt >> 1][2 + (nt & 1)] };
                    mma_bf16(acc[mt][nt], ah[mt], bh2);
                    mma_bf16(acc[mt][nt], ah[mt], bl2);
                    mma_bf16(acc[mt][nt], al[mt], bh2);
                }
            }
        }
        __syncthreads();
    }

    // epilogue: direct global stores (fp32)
    #pragma unroll
    for (int mt = 0; mt < 4; mt++) {
        int m0 = row0 + wm + mt * 16 + (lane >> 2);
        #pragma unroll
        for (int nt = 0; nt < 4; nt++) {
            int n0 = col0 + wn + nt * 8 + (lane & 3) * 2;
            *(float2*)&C[(size_t)m0 * Ntot + n0]       = make_float2(acc[mt][nt][0], acc[mt][nt][1]);
            *(float2*)&C[(size_t)(m0 + 8) * Ntot + n0] = make_float2(acc[mt][nt][2], acc[mt][nt][3]);
        }
    }
}

// =====================================================================
// Flash attention: causal, online softmax (fp32) — unchanged.
// =====================================================================
#define PAD 68

__global__ __launch_bounds__(256)
void attn_kernel(const float* __restrict__ gq, const float* __restrict__ gk,
                 const float* __restrict__ gv, float* __restrict__ go) {
    extern __shared__ float smf[];
    float* Qt = smf;
    float* Kt = Qt + 64*PAD;
    float* Vs = Kt + 64*PAD;
    float* Ps = Vs + 64*PAD;

    const int tid = threadIdx.x;
    const int tx = tid & 15, ty = tid >> 4;
    const int qt = blockIdx.x, h = blockIdx.y, b = blockIdx.z;
    const int kvh = h >> 2;
    const int q0 = qt * 64;

    const float* qbase = gq + (size_t)b * SS * (NH*DH)  + h   * DH;
    const float* kbase = gk + (size_t)b * SS * (NKV*DH) + kvh * DH;
    const float* vbase = gv + (size_t)b * SS * (NKV*DH) + kvh * DH;

    #pragma unroll
    for (int l = 0; l < 4; l++) {
        int fid = tid + l * 256;
        int row = fid >> 4;
        int c4  = (fid & 15) << 2;
        float4 v = *(const float4*)(qbase + (size_t)(q0 + row) * (NH*DH) + c4);
        Qt[(c4+0)*PAD + row] = v.x;
        Qt[(c4+1)*PAD + row] = v.y;
        Qt[(c4+2)*PAD + row] = v.z;
        Qt[(c4+3)*PAD + row] = v.w;
    }

    float m_i[4], l_i[4], o[4][4];
    #pragma unroll
    for (int r = 0; r < 4; r++) {
        m_i[r] = -1e30f; l_i[r] = 0.f;
        #pragma unroll
        for (int c = 0; c < 4; c++) o[r][c] = 0.f;
    }

    for (int j = 0; j <= qt; j++) {
        const int k0 = j * 64;
        __syncthreads();
        #pragma unroll
        for (int l = 0; l < 4; l++) {
            int fid = tid + l * 256;
            int row = fid >> 4;
            int c4  = (fid & 15) << 2;
            float4 kv = *(const float4*)(kbase + (size_t)(k0 + row) * (NKV*DH) + c4);
            Kt[(c4+0)*PAD + row] = kv.x;
            Kt[(c4+1)*PAD + row] = kv.y;
            Kt[(c4+2)*PAD + row] = kv.z;
            Kt[(c4+3)*PAD + row] = kv.w;
            float4 vv = *(const float4*)(vbase + (size_t)(k0 + row) * (NKV*DH) + c4);
            *(float4*)&Vs[row*PAD + c4] = vv;
        }
        __syncthreads();

        float s[4][4];
        #pragma unroll
        for (int r = 0; r < 4; r++)
            #pragma unroll
            for (int c = 0; c < 4; c++) s[r][c] = 0.f;
        #pragma unroll 8
        for (int kk = 0; kk < 64; kk++) {
            float4 a = *(const float4*)&Qt[kk*PAD + ty*4];
            float4 bk = *(const float4*)&Kt[kk*PAD + tx*4];
            float av[4] = {a.x, a.y, a.z, a.w};
            float bv[4] = {bk.x, bk.y, bk.z, bk.w};
            #pragma unroll
            for (int r = 0; r < 4; r++)
                #pragma unroll
                for (int c = 0; c < 4; c++)
                    s[r][c] += av[r] * bv[c];
        }

        const bool diag = (j == qt);
        #pragma unroll
        for (int r = 0; r < 4; r++) {
            int qg = q0 + ty*4 + r;
            #pragma unroll
            for (int c = 0; c < 4; c++) {
                float val = s[r][c] * 0.125f;
                if (diag && (k0 + tx*4 + c) > qg) val = -1e30f;
                s[r][c] = val;
            }
        }

        #pragma unroll
        for (int r = 0; r < 4; r++) {
            float mt = fmaxf(fmaxf(s[r][0], s[r][1]), fmaxf(s[r][2], s[r][3]));
            #pragma unroll
            for (int off = 8; off > 0; off >>= 1)
                mt = fmaxf(mt, __shfl_xor_sync(0xffffffffu, mt, off));
            float mnew = fmaxf(m_i[r], mt);
            float alpha = __expf(m_i[r] - mnew);
            m_i[r] = mnew;
            float rs = 0.f;
            #pragma unroll
            for (int c = 0; c < 4; c++) {
                float p = __expf(s[r][c] - mnew);
                s[r][c] = p;
                rs += p;
            }
            #pragma unroll
            for (int off = 8; off > 0; off >>= 1)
                rs += __shfl_xor_sync(0xffffffffu, rs, off);
            l_i[r] = l_i[r] * alpha + rs;
            #pragma unroll
            for (int c = 0; c < 4; c++) o[r][c] *= alpha;
        }

        #pragma unroll
        for (int r = 0; r < 4; r++)
            *(float4*)&Ps[(ty*4 + r)*PAD + tx*4] =
                make_float4(s[r][0], s[r][1], s[r][2], s[r][3]);
        __syncthreads();

        #pragma unroll 4
        for (int kk = 0; kk < 64; kk += 4) {
            float4 vv[4];
            #pragma unroll
            for (int i = 0; i < 4; i++)
                vv[i] = *(const float4*)&Vs[(kk+i)*PAD + tx*4];
            #pragma unroll
            for (int r = 0; r < 4; r++) {
                float4 p = *(const float4*)&Ps[(ty*4 + r)*PAD + kk];
                o[r][0] += p.x*vv[0].x + p.y*vv[1].x + p.z*vv[2].x + p.w*vv[3].x;
                o[r][1] += p.x*vv[0].y + p.y*vv[1].y + p.z*vv[2].y + p.w*vv[3].y;
                o[r][2] += p.x*vv[0].z + p.y*vv[1].z + p.z*vv[2].z + p.w*vv[3].z;
                o[r][3] += p.x*vv[0].w + p.y*vv[1].w + p.z*vv[2].w + p.w*vv[3].w;
            }
        }
    }

    #pragma unroll
    for (int r = 0; r < 4; r++) {
        float inv = 1.f / l_i[r];
        float* orow = go + (size_t)((size_t)b*SS + q0 + ty*4 + r) * (NH*DH) + h*DH + tx*4;
        *(float4*)orow = make_float4(o[r][0]*inv, o[r][1]*inv, o[r][2]*inv, o[r][3]*inv);
    }
}

// =====================================================================
// Host launcher
// =====================================================================
extern "C" void kernel_launch(void* const* d_in, const int* in_sizes, int n_in,
                              void* d_out, int out_size) {
    const float* residual = (const float*)d_in[0];
    const float* W_Q = (const float*)d_in[1];
    const float* W_K = (const float*)d_in[2];
    const float* W_V = (const float*)d_in[3];
    const float* W_O = (const float*)d_in[4];
    float* out = (float*)d_out;

    float *qp, *kp, *vp, *ap;
    cudaGetSymbolAddress((void**)&qp, g_q);
    cudaGetSymbolAddress((void**)&kp, g_k);
    cudaGetSymbolAddress((void**)&vp, g_v);
    cudaGetSymbolAddress((void**)&ap, g_attn);

    __nv_bfloat16 *Rh, *Rl, *WQh, *WQl, *WKh, *WKl, *WVh, *WVl, *WOTh, *WOTl, *Ahp, *Alp;
    cudaGetSymbolAddress((void**)&Rh,  g_Rh);   cudaGetSymbolAddress((void**)&Rl,  g_Rl);
    cudaGetSymbolAddress((void**)&WQh, g_WQh);  cudaGetSymbolAddress((void**)&WQl, g_WQl);
    cudaGetSymbolAddress((void**)&WKh, g_WKh);  cudaGetSymbolAddress((void**)&WKl, g_WKl);
    cudaGetSymbolAddress((void**)&WVh, g_WVh);  cudaGetSymbolAddress((void**)&WVl, g_WVl);
    cudaGetSymbolAddress((void**)&WOTh, g_WOTh); cudaGetSymbolAddress((void**)&WOTl, g_WOTl);
    cudaGetSymbolAddress((void**)&Ahp, g_Ah);   cudaGetSymbolAddress((void**)&Alp, g_Al);

    cudaFuncSetAttribute(gemm_hmma, cudaFuncAttributeMaxDynamicSharedMemorySize, GSMEM);

    // fp32 -> bf16 hi/lo splits
    split_kernel<<<(MTOK*DM/4 + 255)/256, 256>>>(residual, Rh, Rl, MTOK*DM/4);
    split_kernel<<<(2048*DM/4 + 255)/256, 256>>>(W_Q, WQh, WQl, 2048*DM/4);
    split_kernel<<<(512*DM/4 + 255)/256, 256>>>(W_K, WKh, WKl, 512*DM/4);
    split_kernel<<<(512*DM/4 + 255)/256, 256>>>(W_V, WVh, WVl, 512*DM/4);
    transpose_split_kernel<<<dim3(64, 64), dim3(32, 8)>>>(W_O, WOTh, WOTl);

    // QKV projections (mma.sync bf16-split NT GEMM)
    gemm_hmma<<<dim3(2048/128, MTOK/128), 256, GSMEM>>>(Rh, Rl, WQh, WQl, qp, 2048);
    gemm_hmma<<<dim3(512/128,  MTOK/128), 256, GSMEM>>>(Rh, Rl, WKh, WKl, kp, 512);
    gemm_hmma<<<dim3(512/128,  MTOK/128), 256, GSMEM>>>(Rh, Rl, WVh, WVl, vp, 512);

    // Flash attention (causal, GQA, fp32)
    const int SMEM = 4 * 64 * PAD * (int)sizeof(float);
    cudaFuncSetAttribute(attn_kernel, cudaFuncAttributeMaxDynamicSharedMemorySize, SMEM);
    attn_kernel<<<dim3(SS/64, NH, BB), 256, SMEM>>>(qp, kp, vp, ap);

    // Output projection: out = attn @ W_O == attn @ (W_O^T)^T (NT with WOT)
    split_kernel<<<(MTOK*DM/4 + 255)/256, 256>>>(ap, Ahp, Alp, MTOK*DM/4);
    gemm_hmma<<<dim3(2048/128, MTOK/128), 256, GSMEM>>>(Ahp, Alp, WOTh, WOTl, out, 2048);
}

// round 10
// speedup vs baseline: 2.8242x; 1.6750x over previous
#include <cuda_runtime.h>
#include <cuda_bf16.h>
#include <math.h>
#include <stdint.h>

// Problem constants
#define BB   2
#define SS   2048
#define DM   2048
#define NH   32
#define NKV  8
#define DH   64
#define MTOK (BB*SS)        // 4096 tokens

// ---------------------------------------------------------------------
// Scratch (device globals: allocation-free rule)
// ---------------------------------------------------------------------
__device__ __nv_bfloat16 g_Rh[MTOK * DM];
__device__ __nv_bfloat16 g_Rl[MTOK * DM];
__device__ __nv_bfloat16 g_WQh[2048 * DM];
__device__ __nv_bfloat16 g_WQl[2048 * DM];
__device__ __nv_bfloat16 g_WKh[512 * DM];
__device__ __nv_bfloat16 g_WKl[512 * DM];
__device__ __nv_bfloat16 g_WVh[512 * DM];
__device__ __nv_bfloat16 g_WVl[512 * DM];
__device__ __nv_bfloat16 g_WOTh[2048 * 2048];   // W_O transposed: [d][nh]
__device__ __nv_bfloat16 g_WOTl[2048 * 2048];

// projection outputs, bf16 hi/lo (written directly by GEMM epilogue)
__device__ __nv_bfloat16 g_Qh[MTOK * (NH*DH)];
__device__ __nv_bfloat16 g_Ql[MTOK * (NH*DH)];
__device__ __nv_bfloat16 g_Kh[MTOK * (NKV*DH)];
__device__ __nv_bfloat16 g_Kl[MTOK * (NKV*DH)];
__device__ __nv_bfloat16 g_Vh[MTOK * (NKV*DH)];
__device__ __nv_bfloat16 g_Vl[MTOK * (NKV*DH)];

// attention output, bf16 hi/lo (written directly by attention epilogue)
__device__ __nv_bfloat16 g_Ah[MTOK * (NH*DH)];
__device__ __nv_bfloat16 g_Al[MTOK * (NH*DH)];

// ---------------------------------------------------------------------
// helpers
// ---------------------------------------------------------------------
__device__ __forceinline__ uint32_t smem_u32(const void* p) {
    uint32_t a;
    asm("{ .reg .u64 t; cvta.to.shared.u64 t, %1; cvt.u32.u64 %0, t; }" : "=r"(a) : "l"(p));
    return a;
}
__device__ __forceinline__ void cp_async16(uint32_t dst, const void* src) {
    asm volatile("cp.async.cg.shared.global [%0], [%1], 16;" :: "r"(dst), "l"(src));
}
#define CP_COMMIT()  asm volatile("cp.async.commit_group;" ::: "memory")
#define CP_WAIT1()   asm volatile("cp.async.wait_group 1;" ::: "memory")

__device__ __forceinline__ void ldsm_x4(uint32_t addr, uint32_t& r0, uint32_t& r1,
                                        uint32_t& r2, uint32_t& r3) {
    asm volatile("ldmatrix.sync.aligned.m8n8.x4.shared.b16 {%0,%1,%2,%3}, [%4];"
                 : "=r"(r0), "=r"(r1), "=r"(r2), "=r"(r3) : "r"(addr));
}
__device__ __forceinline__ void ldsm_x4_t(uint32_t addr, uint32_t& r0, uint32_t& r1,
                                          uint32_t& r2, uint32_t& r3) {
    asm volatile("ldmatrix.sync.aligned.m8n8.x4.trans.shared.b16 {%0,%1,%2,%3}, [%4];"
                 : "=r"(r0), "=r"(r1), "=r"(r2), "=r"(r3) : "r"(addr));
}
__device__ __forceinline__ void mma_bf16(float* d, const uint32_t* a, uint32_t b0, uint32_t b1) {
    asm volatile(
        "mma.sync.aligned.m16n8k16.row.col.f32.bf16.bf16.f32 "
        "{%0,%1,%2,%3}, {%4,%5,%6,%7}, {%8,%9}, {%0,%1,%2,%3};"
        : "+f"(d[0]), "+f"(d[1]), "+f"(d[2]), "+f"(d[3])
        : "r"(a[0]), "r"(a[1]), "r"(a[2]), "r"(a[3]), "r"(b0), "r"(b1));
}

__device__ __forceinline__ void bsplit(float v, unsigned short& h, unsigned short& l) {
    __nv_bfloat16 bh = __float2bfloat16(v);
    float r = v - __bfloat162float(bh);
    __nv_bfloat16 bl = __float2bfloat16(r);
    h = *reinterpret_cast<unsigned short*>(&bh);
    l = *reinterpret_cast<unsigned short*>(&bl);
}
__device__ __forceinline__ uint32_t pack_bf2(float lo, float hi) {
    __nv_bfloat162 t = __floats2bfloat162_rn(lo, hi);
    return *reinterpret_cast<uint32_t*>(&t);
}
__device__ __forceinline__ uint32_t bf16_of(float v) {
    __nv_bfloat16 b = __float2bfloat16(v);
    return (uint32_t)*reinterpret_cast<unsigned short*>(&b);
}
__device__ __forceinline__ float bf16_back(uint32_t u) {
    unsigned short s = (unsigned short)u;
    return __bfloat162float(*reinterpret_cast<__nv_bfloat16*>(&s));
}

// ---------------------------------------------------------------------
// fp32 -> bf16 hi/lo split (inputs only)
// ---------------------------------------------------------------------
__global__ __launch_bounds__(256)
void split_kernel(const float* __restrict__ x, __nv_bfloat16* __restrict__ hi,
                  __nv_bfloat16* __restrict__ lo, int n4) {
    int i = blockIdx.x * 256 + threadIdx.x;
    if (i >= n4) return;
    float4 v = ((const float4*)x)[i];
    ushort4 h, l;
    bsplit(v.x, h.x, l.x); bsplit(v.y, h.y, l.y);
    bsplit(v.z, h.z, l.z); bsplit(v.w, h.w, l.w);
    ((ushort4*)hi)[i] = h;
    ((ushort4*)lo)[i] = l;
}

// W_O [nh=2048][d=2048] -> transposed split [d][nh]
__global__ __launch_bounds__(256)
void transpose_split_kernel(const float* __restrict__ W,
                            __nv_bfloat16* __restrict__ th,
                            __nv_bfloat16* __restrict__ tl) {
    __shared__ float t[32][33];
    int bx = blockIdx.x * 32, by = blockIdx.y * 32;
    int txx = threadIdx.x, tyy = threadIdx.y;   // block (32, 8)
    #pragma unroll
    for (int j = 0; j < 4; j++)
        t[tyy + 8*j][txx] = W[(size_t)(by + tyy + 8*j) * 2048 + bx + txx];
    __syncthreads();
    #pragma unroll
    for (int j = 0; j < 4; j++) {
        int orow = bx + tyy + 8*j;
        int ocol = by + txx;
        float v = t[txx][tyy + 8*j];
        unsigned short h, l;
        bsplit(v, h, l);
        th[(size_t)orow * 2048 + ocol] = *reinterpret_cast<__nv_bfloat16*>(&h);
        tl[(size_t)orow * 2048 + ocol] = *reinterpret_cast<__nv_bfloat16*>(&l);
    }
}

// ---------------------------------------------------------------------
// mma.sync bf16-split GEMM NT:  C[128,128] tile = A[128,K] @ B[128,K]^T
// SPLIT_OUT=0: fp32 C.  SPLIT_OUT=1: bf16 hi/lo pair output.
// ---------------------------------------------------------------------
#define BK        64
#define NKCHUNK   (DM / BK)          // 32
#define TILE_B    (128 * BK * 2)     // 16384
#define STG_B     (4 * TILE_B)       // 64KB
#define NSTAGE    3
#define GSMEM     (NSTAGE * STG_B)   // 192KB

template<int SPLIT_OUT>
__global__ __launch_bounds__(256)
void gemm_hmma(const __nv_bfloat16* __restrict__ Ah, const __nv_bfloat16* __restrict__ Al,
               const __nv_bfloat16* __restrict__ Bh, const __nv_bfloat16* __restrict__ Bl,
               float* __restrict__ C, __nv_bfloat16* __restrict__ Ch,
               __nv_bfloat16* __restrict__ Cl, int Ntot) {
    extern __shared__ char sm[];
    const uint32_t sb = smem_u32(sm);
    const int tid = threadIdx.x, wid = tid >> 5, lane = tid & 31;
    const int col0 = blockIdx.x * 128, row0 = blockIdx.y * 128;
    const int wm = (wid >> 2) * 64;
    const int wn = (wid & 3) * 32;

    const char* gAh = (const char*)Ah + (size_t)row0 * 4096;
    const char* gAl = (const char*)Al + (size_t)row0 * 4096;
    const char* gBh = (const char*)Bh + (size_t)col0 * 4096;
    const char* gBl = (const char*)Bl + (size_t)col0 * 4096;

    auto sw = [](int r, int g) -> uint32_t {
        return (uint32_t)(r * 128 + ((g * 16) ^ ((r & 7) << 4)));
    };
    const int lrow = ((lane >> 3) & 1) * 8 + (lane & 7);
    const int lkb  = (lane >> 4) * 16;

    float acc[4][4][4];
    #pragma unroll
    for (int mt = 0; mt < 4; mt++)
        #pragma unroll
        for (int nt = 0; nt < 4; nt++)
            #pragma unroll
            for (int e = 0; e < 4; e++) acc[mt][nt][e] = 0.f;

    auto load_stage = [&](int stage, int chunk) {
        uint32_t s0 = sb + stage * STG_B;
        const size_t kb0 = (size_t)chunk * 128;
        #pragma unroll
        for (int t = 0; t < 4; t++) {
            int idx = tid + t * 256;
            int r = idx >> 3, g = idx & 7;
            uint32_t so = sw(r, g);
            size_t go = (size_t)r * 4096 + kb0 + g * 16;
            cp_async16(s0 + 0*TILE_B + so, gAh + go);
            cp_async16(s0 + 1*TILE_B + so, gAl + go);
            cp_async16(s0 + 2*TILE_B + so, gBh + go);
            cp_async16(s0 + 3*TILE_B + so, gBl + go);
        }
    };

    load_stage(0, 0); CP_COMMIT();
    load_stage(1, 1); CP_COMMIT();

    for (int i = 0; i < NKCHUNK; i++) {
        CP_WAIT1();
        __syncthreads();
        if (i + 2 < NKCHUNK) load_stage((i + 2) % NSTAGE, i + 2);
        CP_COMMIT();

        uint32_t s0 = sb + (i % NSTAGE) * STG_B;
        uint32_t aH = s0 + 0*TILE_B, aL = s0 + 1*TILE_B;
        uint32_t bH = s0 + 2*TILE_B, bL = s0 + 3*TILE_B;

        #pragma unroll
        for (int ks = 0; ks < 4; ks++) {
            const int kb = ks * 32 + lkb;
            uint32_t ah[4][4], al[4][4];
            #pragma unroll
            for (int mt = 0; mt < 4; mt++) {
                int r = wm + mt * 16 + lrow;
                uint32_t off = (uint32_t)(r * 128 + (kb ^ ((r & 7) << 4)));
                ldsm_x4(aH + off, ah[mt][0], ah[mt][1], ah[mt][2], ah[mt][3]);
                ldsm_x4(aL + off, al[mt][0], al[mt][1], al[mt][2], al[mt][3]);
            }
            uint32_t bhr[2][4], blr[2][4];
            #pragma unroll
            for (int np = 0; np < 2; np++) {
                int r = wn + np * 16 + lrow;
                uint32_t off = (uint32_t)(r * 128 + (kb ^ ((r & 7) << 4)));
                ldsm_x4(bH + off, bhr[np][0], bhr[np][1], bhr[np][2], bhr[np][3]);
                ldsm_x4(bL + off, blr[np][0], blr[np][1], blr[np][2], blr[np][3]);
            }
            #pragma unroll
            for (int mt = 0; mt < 4; mt++) {
                #pragma unroll
                for (int nt = 0; nt < 4; nt++) {
                    uint32_t b0h = bhr[nt >> 1][nt & 1], b1h = bhr[nt >> 1][2 + (nt & 1)];
                    uint32_t b0l = blr[nt >> 1][nt & 1], b1l = blr[nt >> 1][2 + (nt & 1)];
                    mma_bf16(acc[mt][nt], ah[mt], b0h, b1h);
                    mma_bf16(acc[mt][nt], ah[mt], b0l, b1l);
                    mma_bf16(acc[mt][nt], al[mt], b0h, b1h);
                }
            }
        }
        __syncthreads();
    }

    #pragma unroll
    for (int mt = 0; mt < 4; mt++) {
        int m0 = row0 + wm + mt * 16 + (lane >> 2);
        #pragma unroll
        for (int nt = 0; nt < 4; nt++) {
            int n0 = col0 + wn + nt * 8 + (lane & 3) * 2;
            if (SPLIT_OUT) {
                #pragma unroll
                for (int hh = 0; hh < 2; hh++) {
                    size_t idx = (size_t)(m0 + hh * 8) * Ntot + n0;
                    float v0 = acc[mt][nt][hh*2], v1 = acc[mt][nt][hh*2 + 1];
                    uint32_t h0 = bf16_of(v0), h1 = bf16_of(v1);
                    float r0 = v0 - bf16_back(h0), r1 = v1 - bf16_back(h1);
                    *(uint32_t*)&Ch[idx] = h0 | (h1 << 16);
                    *(uint32_t*)&Cl[idx] = bf16_of(r0) | (bf16_of(r1) << 16);
                }
            } else {
                *(float2*)&C[(size_t)m0 * Ntot + n0]       = make_float2(acc[mt][nt][0], acc[mt][nt][1]);
                *(float2*)&C[(size_t)(m0 + 8) * Ntot + n0] = make_float2(acc[mt][nt][2], acc[mt][nt][3]);
            }
        }
    }
}

// =====================================================================
// Tensor-core flash attention (causal, GQA, bf16 3-term split)
// Block: 128 Q rows x one head x one batch. 8 warps, warp = 16 Q rows.
// KV tiles of 64 tokens, double-buffered cp.async.
// =====================================================================
#define ATQ_H  0
#define ATQ_L  16384
#define ATSTG(s) (32768 + (s)*32768)
#define ATK_H  0
#define ATK_L  8192
#define ATV_H  16384
#define ATV_L  24576
#define ATSMEM 98304   // 96KB

__global__ __launch_bounds__(256)
void attn_mma(const __nv_bfloat16* __restrict__ Qh, const __nv_bfloat16* __restrict__ Ql,
              const __nv_bfloat16* __restrict__ Kh, const __nv_bfloat16* __restrict__ Kl,
              const __nv_bfloat16* __restrict__ Vh, const __nv_bfloat16* __restrict__ Vl,
              __nv_bfloat16* __restrict__ Oh, __nv_bfloat16* __restrict__ Ol) {
    extern __shared__ char sm[];
    const uint32_t sb = smem_u32(sm);
    const int tid = threadIdx.x, wid = tid >> 5, lane = tid & 31;
    const int qt = blockIdx.x, h = blockIdx.y, b = blockIdx.z;
    const int kvh = h >> 2;
    const int q0 = qt * 128;

    const char* gQh = (const char*)Qh + ((size_t)(b * SS + q0) * 2048 + h * 64) * 2;
    const char* gQl = (const char*)Ql + ((size_t)(b * SS + q0) * 2048 + h * 64) * 2;
    const char* gKh = (const char*)Kh + ((size_t)b * SS * 512 + kvh * 64) * 2;
    const char* gKl = (const char*)Kl + ((size_t)b * SS * 512 + kvh * 64) * 2;
    const char* gVh = (const char*)Vh + ((size_t)b * SS * 512 + kvh * 64) * 2;
    const char* gVl = (const char*)Vl + ((size_t)b * SS * 512 + kvh * 64) * 2;

    // Q tile: 128 rows x 128B (hi + lo)
    #pragma unroll
    for (int t = 0; t < 4; t++) {
        int idx = tid + t * 256;
        int r = idx >> 3, g = idx & 7;
        uint32_t so = (uint32_t)(r * 128 + ((g * 16) ^ ((r & 7) << 4)));
        cp_async16(sb + ATQ_H + so, gQh + (size_t)r * 4096 + g * 16);
        cp_async16(sb + ATQ_L + so, gQl + (size_t)r * 4096 + g * 16);
    }
    CP_COMMIT();

    auto load_kv = [&](int stage, int tile) {
        uint32_t s0 = sb + ATSTG(stage);
        #pragma unroll
        for (int t = 0; t < 2; t++) {
            int idx = tid + t * 256;
            int r = idx >> 3, g = idx & 7;
            uint32_t so = (uint32_t)(r * 128 + ((g * 16) ^ ((r & 7) << 4)));
            size_t go = (size_t)(tile * 64 + r) * 1024 + g * 16;
            cp_async16(s0 + ATK_H + so, gKh + go);
            cp_async16(s0 + ATK_L + so, gKl + go);
            cp_async16(s0 + ATV_H + so, gVh + go);
            cp_async16(s0 + ATV_L + so, gVl + go);
        }
    };

    const int ntiles = 2 * qt + 2;
    load_kv(0, 0); CP_COMMIT();

    // wait for Q (<=1 pending: stage0 may still be in flight)
    CP_WAIT1();
    __syncthreads();

    // Q fragments: persistent in registers (16 rows x 64 k per warp)
    const int lrow = ((lane >> 3) & 1) * 8 + (lane & 7);
    const int lkb  = (lane >> 4) * 16;
    uint32_t qfh[4][4], qfl[4][4];
    #pragma unroll
    for (int kc = 0; kc < 4; kc++) {
        int r = wid * 16 + lrow;
        uint32_t off = (uint32_t)(r * 128 + ((kc * 32 + lkb) ^ ((r & 7) << 4)));
        ldsm_x4(sb + ATQ_H + off, qfh[kc][0], qfh[kc][1], qfh[kc][2], qfh[kc][3]);
        ldsm_x4(sb + ATQ_L + off, qfl[kc][0], qfl[kc][1], qfl[kc][2], qfl[kc][3]);
    }

    load_kv(1, 1); CP_COMMIT();

    float m0 = -1e30f, m1 = -1e30f, l0 = 0.f, l1 = 0.f;
    float oacc[8][4];
    #pragma unroll
    for (int nt = 0; nt < 8; nt++)
        #pragma unroll
        for (int e = 0; e < 4; e++) oacc[nt][e] = 0.f;

    const int row0 = q0 + wid * 16 + (lane >> 2);
    const int row1 = row0 + 8;

    for (int j = 0; j < ntiles; j++) {
        CP_WAIT1();
        __syncthreads();

        uint32_t stg = sb + ATSTG(j & 1);

        // ---- S = Q K^T (3-term split), 16x64 per warp ----
        float sacc[8][4];
        #pragma unroll
        for (int nt = 0; nt < 8; nt++)
            #pragma unroll
            for (int e = 0; e < 4; e++) sacc[nt][e] = 0.f;

        #pragma unroll
        for (int kc = 0; kc < 4; kc++) {
            const int kb = kc * 32 + lkb;
            #pragma unroll
            for (int np = 0; np < 4; np++) {
                int r = np * 16 + lrow;
                uint32_t off = (uint32_t)(r * 128 + (kb ^ ((r & 7) << 4)));
                uint32_t kh0, kh1, kh2, kh3, kl0, kl1, kl2, kl3;
                ldsm_x4(stg + ATK_H + off, kh0, kh1, kh2, kh3);
                ldsm_x4(stg + ATK_L + off, kl0, kl1, kl2, kl3);
                mma_bf16(sacc[np*2+0], qfh[kc], kh0, kh2);
                mma_bf16(sacc[np*2+0], qfh[kc], kl0, kl2);
                mma_bf16(sacc[np*2+0], qfl[kc], kh0, kh2);
                mma_bf16(sacc[np*2+1], qfh[kc], kh1, kh3);
                mma_bf16(sacc[np*2+1], qfh[kc], kl1, kl3);
                mma_bf16(sacc[np*2+1], qfl[kc], kh1, kh3);
            }
        }

        // ---- scale + causal mask ----
        const int tok0 = j * 64;
        #pragma unroll
        for (int nt = 0; nt < 8; nt++)
            #pragma unroll
            for (int e = 0; e < 4; e++) sacc[nt][e] *= 0.125f;
        if (j >= 2 * qt) {   // diagonal-overlap tiles only
            #pragma unroll
            for (int nt = 0; nt < 8; nt++) {
                int colb = tok0 + nt * 8 + (lane & 3) * 2;
                if (colb     > row0) sacc[nt][0] = -1e30f;
                if (colb + 1 > row0) sacc[nt][1] = -1e30f;
                if (colb     > row1) sacc[nt][2] = -1e30f;
                if (colb + 1 > row1) sacc[nt][3] = -1e30f;
            }
        }

        // ---- online softmax (rows owned by lane quads) ----
        float mx0 = -1e30f, mx1 = -1e30f;
        #pragma unroll
        for (int nt = 0; nt < 8; nt++) {
            mx0 = fmaxf(mx0, fmaxf(sacc[nt][0], sacc[nt][1]));
            mx1 = fmaxf(mx1, fmaxf(sacc[nt][2], sacc[nt][3]));
        }
        mx0 = fmaxf(mx0, __shfl_xor_sync(0xffffffffu, mx0, 1));
        mx0 = fmaxf(mx0, __shfl_xor_sync(0xffffffffu, mx0, 2));
        mx1 = fmaxf(mx1, __shfl_xor_sync(0xffffffffu, mx1, 1));
        mx1 = fmaxf(mx1, __shfl_xor_sync(0xffffffffu, mx1, 2));
        float mn0 = fmaxf(m0, mx0), mn1 = fmaxf(m1, mx1);
        float a0 = __expf(m0 - mn0), a1 = __expf(m1 - mn1);
        m0 = mn0; m1 = mn1;

        float rs0 = 0.f, rs1 = 0.f;
        #pragma unroll
        for (int nt = 0; nt < 8; nt++) {
            sacc[nt][0] = __expf(sacc[nt][0] - mn0);
            sacc[nt][1] = __expf(sacc[nt][1] - mn0);
            sacc[nt][2] = __expf(sacc[nt][2] - mn1);
            sacc[nt][3] = __expf(sacc[nt][3] - mn1);
            rs0 += sacc[nt][0] + sacc[nt][1];
            rs1 += sacc[nt][2] + sacc[nt][3];
        }
        rs0 += __shfl_xor_sync(0xffffffffu, rs0, 1);
        rs0 += __shfl_xor_sync(0xffffffffu, rs0, 2);
        rs1 += __shfl_xor_sync(0xffffffffu, rs1, 1);
        rs1 += __shfl_xor_sync(0xffffffffu, rs1, 2);
        l0 = l0 * a0 + rs0;
        l1 = l1 * a1 + rs1;

        #pragma unroll
        for (int nt = 0; nt < 8; nt++) {
            oacc[nt][0] *= a0; oacc[nt][1] *= a0;
            oacc[nt][2] *= a1; oacc[nt][3] *= a1;
        }

        // ---- O += P V (P frags from registers; V via ldmatrix.trans) ----
        #pragma unroll
        for (int tc = 0; tc < 4; tc++) {
            // P A-fragment (hi/lo split) for tokens tc*16..tc*16+15
            uint32_t pfh[4], pfl[4];
            #pragma unroll
            for (int q = 0; q < 4; q++) {
                const int nt = tc * 2 + (q >> 1);
                const int e0 = (q & 1) * 2;
                float v0 = sacc[nt][e0], v1 = sacc[nt][e0 + 1];
                uint32_t h0 = bf16_of(v0), h1 = bf16_of(v1);
                // order: pfh[0]=rows0-7 k0-7, pfh[1]=rows8-15 k0-7, pfh[2]=rows0-7 k8-15, pfh[3]=rows8-15 k8-15
                int slot = (q >> 1) * 2 + (q & 1);       // 0..3 matches (nt-half, row-half)
                pfh[slot] = h0 | (h1 << 16);
                pfl[slot] = bf16_of(v0 - bf16_back(h0)) | (bf16_of(v1 - bf16_back(h1)) << 16);
            }
            // fix ordering: a0=(r0-7,k0-7), a1=(r8-15,k0-7), a2=(r0-7,k8-15), a3=(r8-15,k8-15)
            // built: slot0 = (nt=2tc, e0=0) rows0-7 k0-7 ✓; slot1 = (nt=2tc, e0=2) rows8-15 k0-7 ✓;
            //        slot2 = (nt=2tc+1, e0=0) rows0-7 k8-15 ✓; slot3 ✓.
            #pragma unroll
            for (int nh = 0; nh < 4; nh++) {
                int r = tc * 16 + lrow;
                uint32_t off = (uint32_t)(r * 128 + ((nh * 32 + lkb) ^ ((r & 7) << 4)));
                uint32_t vh0, vh1, vh2, vh3, vl0, vl1, vl2, vl3;
                ldsm_x4_t(stg + ATV_H + off, vh0, vh1, vh2, vh3);
                ldsm_x4_t(stg + ATV_L + off, vl0, vl1, vl2, vl3);
                mma_bf16(oacc[nh*2+0], pfh, vh0, vh1);
                mma_bf16(oacc[nh*2+0], pfh, vl0, vl1);
                mma_bf16(oacc[nh*2+0], pfl, vh0, vh1);
                mma_bf16(oacc[nh*2+1], pfh, vh2, vh3);
                mma_bf16(oacc[nh*2+1], pfh, vl2, vl3);
                mma_bf16(oacc[nh*2+1], pfl, vh2, vh3);
            }
        }

        __syncthreads();
        if (j + 2 < ntiles) load_kv(j & 1, j + 2);
        CP_COMMIT();
    }

    // ---- epilogue: normalize, split to bf16 hi/lo, store ----
    float inv0 = 1.f / l0, inv1 = 1.f / l1;
    #pragma unroll
    for (int nt = 0; nt < 8; nt++) {
        int col = nt * 8 + (lane & 3) * 2;
        #pragma unroll
        for (int hh = 0; hh < 2; hh++) {
            int grow = (hh == 0) ? row0 : row1;
            float inv = (hh == 0) ? inv0 : inv1;
            float v0 = oacc[nt][hh*2] * inv, v1 = oacc[nt][hh*2 + 1] * inv;
            size_t idx = (size_t)(b * SS + grow) * 2048 + h * 64 + col;
            uint32_t h0 = bf16_of(v0), h1 = bf16_of(v1);
            *(uint32_t*)&Oh[idx] = h0 | (h1 << 16);
            *(uint32_t*)&Ol[idx] = bf16_of(v0 - bf16_back(h0)) | (bf16_of(v1 - bf16_back(h1)) << 16);
        }
    }
}

// =====================================================================
// Host launcher
// =====================================================================
extern "C" void kernel_launch(void* const* d_in, const int* in_sizes, int n_in,
                              void* d_out, int out_size) {
    const float* residual = (const float*)d_in[0];
    const float* W_Q = (const float*)d_in[1];
    const float* W_K = (const float*)d_in[2];
    const float* W_V = (const float*)d_in[3];
    const float* W_O = (const float*)d_in[4];
    float* out = (float*)d_out;

    __nv_bfloat16 *Rh, *Rl, *WQh, *WQl, *WKh, *WKl, *WVh, *WVl, *WOTh, *WOTl;
    __nv_bfloat16 *Qh, *Ql, *Kh, *Kl, *Vh, *Vl, *Ah, *Al;
    cudaGetSymbolAddress((void**)&Rh,  g_Rh);   cudaGetSymbolAddress((void**)&Rl,  g_Rl);
    cudaGetSymbolAddress((void**)&WQh, g_WQh);  cudaGetSymbolAddress((void**)&WQl, g_WQl);
    cudaGetSymbolAddress((void**)&WKh, g_WKh);  cudaGetSymbolAddress((void**)&WKl, g_WKl);
    cudaGetSymbolAddress((void**)&WVh, g_WVh);  cudaGetSymbolAddress((void**)&WVl, g_WVl);
    cudaGetSymbolAddress((void**)&WOTh, g_WOTh); cudaGetSymbolAddress((void**)&WOTl, g_WOTl);
    cudaGetSymbolAddress((void**)&Qh, g_Qh);    cudaGetSymbolAddress((void**)&Ql, g_Ql);
    cudaGetSymbolAddress((void**)&Kh, g_Kh);    cudaGetSymbolAddress((void**)&Kl, g_Kl);
    cudaGetSymbolAddress((void**)&Vh, g_Vh);    cudaGetSymbolAddress((void**)&Vl, g_Vl);
    cudaGetSymbolAddress((void**)&Ah, g_Ah);    cudaGetSymbolAddress((void**)&Al, g_Al);

    cudaFuncSetAttribute(gemm_hmma<0>, cudaFuncAttributeMaxDynamicSharedMemorySize, GSMEM);
    cudaFuncSetAttribute(gemm_hmma<1>, cudaFuncAttributeMaxDynamicSharedMemorySize, GSMEM);
    cudaFuncSetAttribute(attn_mma, cudaFuncAttributeMaxDynamicSharedMemorySize, ATSMEM);

    // fp32 -> bf16 hi/lo splits (inputs)
    split_kernel<<<(MTOK*DM/4 + 255)/256, 256>>>(residual, Rh, Rl, MTOK*DM/4);
    split_kernel<<<(2048*DM/4 + 255)/256, 256>>>(W_Q, WQh, WQl, 2048*DM/4);
    split_kernel<<<(512*DM/4 + 255)/256, 256>>>(W_K, WKh, WKl, 512*DM/4);
    split_kernel<<<(512*DM/4 + 255)/256, 256>>>(W_V, WVh, WVl, 512*DM/4);
    transpose_split_kernel<<<dim3(64, 64), dim3(32, 8)>>>(W_O, WOTh, WOTl);

    // QKV projections -> bf16 hi/lo outputs directly
    gemm_hmma<1><<<dim3(2048/128, MTOK/128), 256, GSMEM>>>(Rh, Rl, WQh, WQl, nullptr, Qh, Ql, 2048);
    gemm_hmma<1><<<dim3(512/128,  MTOK/128), 256, GSMEM>>>(Rh, Rl, WKh, WKl, nullptr, Kh, Kl, 512);
    gemm_hmma<1><<<dim3(512/128,  MTOK/128), 256, GSMEM>>>(Rh, Rl, WVh, WVl, nullptr, Vh, Vl, 512);

    // Tensor-core flash attention -> bf16 hi/lo attention output
    attn_mma<<<dim3(SS/128, NH, BB), 256, ATSMEM>>>(Qh, Ql, Kh, Kl, Vh, Vl, Ah, Al);

    // Output projection -> fp32 out
    gemm_hmma<0><<<dim3(2048/128, MTOK/128), 256, GSMEM>>>(Ah, Al, WOTh, WOTl, out, nullptr, nullptr, 2048);
}